// round 1
// baseline (speedup 1.0000x reference)
#include <cuda_runtime.h>
#include <cuda_bf16.h>
#include <math.h>

#define BATCH 4
#define CCH   512
#define HW    4096
#define NGRP  32
#define CPG   16   // channels per group

// ---------------- scratch (device globals; no allocation) ----------------
__device__ float g_xn [(size_t)BATCH * CCH * HW];          //  32 MB
__device__ float g_qkv[(size_t)BATCH * 3 * CCH * HW];      //  96 MB
__device__ float g_sc [(size_t)BATCH * HW * HW];           // 256 MB
__device__ float g_ao [(size_t)BATCH * CCH * HW];          //  32 MB

// ---------------- GroupNorm ----------------
// grid = BATCH*NGRP blocks, 256 threads. Each block handles one (b,g):
// 16 channels x 4096 = 65536 floats.
__global__ __launch_bounds__(256) void gn_kernel(const float* __restrict__ x,
                                                 const float* __restrict__ w,
                                                 const float* __restrict__ bias) {
    int bg = blockIdx.x;
    int b = bg / NGRP, g = bg % NGRP;
    const size_t base = ((size_t)(b * CCH + g * CPG)) * HW;
    const float4* x4 = (const float4*)(x + base);
    float4* o4 = (float4*)(g_xn + base);
    int t = threadIdx.x;
    const int N4 = (CPG * HW) / 4; // 16384 float4s

    float s = 0.f, ss = 0.f;
    for (int i = t; i < N4; i += 256) {
        float4 v = x4[i];
        s  += v.x + v.y + v.z + v.w;
        ss += v.x * v.x + v.y * v.y + v.z * v.z + v.w * v.w;
    }
    __shared__ float sh0[256], sh1[256];
    sh0[t] = s; sh1[t] = ss;
    __syncthreads();
    for (int off = 128; off; off >>= 1) {
        if (t < off) { sh0[t] += sh0[t + off]; sh1[t] += sh1[t + off]; }
        __syncthreads();
    }
    const float inv = 1.f / (float)(CPG * HW);
    float mean = sh0[0] * inv;
    float var  = sh1[0] * inv - mean * mean;
    float rstd = rsqrtf(var + 1e-5f);

    for (int i = t; i < N4; i += 256) {
        int c = g * CPG + ((i * 4) >> 12);   // HW = 4096
        float sw = w[c] * rstd;
        float sb = bias[c] - mean * sw;
        float4 v = x4[i];
        float4 o;
        o.x = v.x * sw + sb; o.y = v.y * sw + sb;
        o.z = v.z * sw + sb; o.w = v.w * sw + sb;
        o4[i] = o;
    }
}

// ---------------- generic tiled fp32 GEMM ----------------
// C[m,n] = alpha * sum_k A(k,m)*B(k,n)  (+ epilogue)
// TA=false: A stored as [K x M] row-major (element A[k*lda+m])
// TA=true : A stored as [M x K] row-major (element A[m*lda+k])
// Same convention for TB / B with n.
// EPI: 0 = alpha only; 1 = +bias[m]; 3 = +bias[m] + resid[m,n]
// Tiles: 128x128x8, 256 threads, 8x8 per thread.
template<bool TA, bool TB, int EPI>
__global__ __launch_bounds__(256) void gemm_kernel(
    const float* __restrict__ A, const float* __restrict__ Bm,
    float* __restrict__ C,
    int Kdim, int lda, int ldb, int ldc,
    size_t sA, size_t sB, size_t sC,
    float alpha, const float* __restrict__ bias,
    const float* __restrict__ resid, size_t sR)
{
    __shared__ float As[8][128];
    __shared__ float Bs[8][128];

    const int bz = blockIdx.z;
    const float* Ab = A  + (size_t)bz * sA;
    const float* Bb = Bm + (size_t)bz * sB;
    float*       Cb = C  + (size_t)bz * sC;

    const int m0 = blockIdx.y * 128;
    const int n0 = blockIdx.x * 128;
    const int t  = threadIdx.x;
    const int ty = t >> 4, tx = t & 15;

    float acc[8][8];
#pragma unroll
    for (int i = 0; i < 8; i++)
#pragma unroll
        for (int j = 0; j < 8; j++) acc[i][j] = 0.f;

    for (int k0 = 0; k0 < Kdim; k0 += 8) {
        if (!TA) {
            int kk = t >> 5, mm = (t & 31) << 2;
            float4 v = *(const float4*)(Ab + (size_t)(k0 + kk) * lda + m0 + mm);
            *(float4*)&As[kk][mm] = v;
        } else {
            int mm = t >> 1, kk = (t & 1) << 2;
            float4 v = *(const float4*)(Ab + (size_t)(m0 + mm) * lda + k0 + kk);
            As[kk + 0][mm] = v.x; As[kk + 1][mm] = v.y;
            As[kk + 2][mm] = v.z; As[kk + 3][mm] = v.w;
        }
        if (!TB) {
            int kk = t >> 5, nn = (t & 31) << 2;
            float4 v = *(const float4*)(Bb + (size_t)(k0 + kk) * ldb + n0 + nn);
            *(float4*)&Bs[kk][nn] = v;
        } else {
            int nn = t >> 1, kk = (t & 1) << 2;
            float4 v = *(const float4*)(Bb + (size_t)(n0 + nn) * ldb + k0 + kk);
            Bs[kk + 0][nn] = v.x; Bs[kk + 1][nn] = v.y;
            Bs[kk + 2][nn] = v.z; Bs[kk + 3][nn] = v.w;
        }
        __syncthreads();

#pragma unroll
        for (int kk = 0; kk < 8; kk++) {
            float a[8], bfr[8];
            *(float4*)&a[0]   = *(float4*)&As[kk][ty * 8];
            *(float4*)&a[4]   = *(float4*)&As[kk][ty * 8 + 4];
            *(float4*)&bfr[0] = *(float4*)&Bs[kk][tx * 8];
            *(float4*)&bfr[4] = *(float4*)&Bs[kk][tx * 8 + 4];
#pragma unroll
            for (int i = 0; i < 8; i++)
#pragma unroll
                for (int j = 0; j < 8; j++)
                    acc[i][j] += a[i] * bfr[j];
        }
        __syncthreads();
    }

#pragma unroll
    for (int i = 0; i < 8; i++) {
        int m = m0 + ty * 8 + i;
        float badd = 0.f;
        if (EPI == 1 || EPI == 3) badd = bias[m];
        float* crow = Cb + (size_t)m * ldc + n0 + tx * 8;
        const float* rrow = nullptr;
        if (EPI == 3) rrow = resid + (size_t)bz * sR + (size_t)m * ldc + n0 + tx * 8;
#pragma unroll
        for (int j = 0; j < 8; j += 4) {
            float4 r;
            r.x = acc[i][j + 0] * alpha + badd;
            r.y = acc[i][j + 1] * alpha + badd;
            r.z = acc[i][j + 2] * alpha + badd;
            r.w = acc[i][j + 3] * alpha + badd;
            if (EPI == 3) {
                float4 rv = *(const float4*)(rrow + j);
                r.x += rv.x; r.y += rv.y; r.z += rv.z; r.w += rv.w;
            }
            *(float4*)(crow + j) = r;
        }
    }
}

// ---------------- row softmax over g_sc ----------------
// one block (256 threads) per row of 4096; row held in registers (16/thread).
__global__ __launch_bounds__(256) void softmax_kernel() {
    float4* row = (float4*)(g_sc + (size_t)blockIdx.x * HW);
    int t = threadIdx.x;
    float4 v[4];
    float mx = -1e30f;
#pragma unroll
    for (int i = 0; i < 4; i++) {
        v[i] = row[t + i * 256];
        mx = fmaxf(mx, fmaxf(fmaxf(v[i].x, v[i].y), fmaxf(v[i].z, v[i].w)));
    }
    __shared__ float sh[8];
#pragma unroll
    for (int o = 16; o; o >>= 1) mx = fmaxf(mx, __shfl_xor_sync(0xffffffffu, mx, o));
    if ((t & 31) == 0) sh[t >> 5] = mx;
    __syncthreads();
    mx = sh[0];
#pragma unroll
    for (int i = 1; i < 8; i++) mx = fmaxf(mx, sh[i]);

    float s = 0.f;
#pragma unroll
    for (int i = 0; i < 4; i++) {
        v[i].x = __expf(v[i].x - mx); v[i].y = __expf(v[i].y - mx);
        v[i].z = __expf(v[i].z - mx); v[i].w = __expf(v[i].w - mx);
        s += v[i].x + v[i].y + v[i].z + v[i].w;
    }
#pragma unroll
    for (int o = 16; o; o >>= 1) s += __shfl_xor_sync(0xffffffffu, s, o);
    __syncthreads();
    if ((t & 31) == 0) sh[t >> 5] = s;
    __syncthreads();
    s = 0.f;
#pragma unroll
    for (int i = 0; i < 8; i++) s += sh[i];
    float inv = 1.f / s;
#pragma unroll
    for (int i = 0; i < 4; i++) {
        v[i].x *= inv; v[i].y *= inv; v[i].z *= inv; v[i].w *= inv;
        row[t + i * 256] = v[i];
    }
}

// ---------------- launch ----------------
extern "C" void kernel_launch(void* const* d_in, const int* in_sizes, int n_in,
                              void* d_out, int out_size) {
    const float* x     = (const float*)d_in[0];
    const float* gn_w  = (const float*)d_in[1];
    const float* gn_b  = (const float*)d_in[2];
    const float* qkv_w = (const float*)d_in[3];
    const float* qkv_b = (const float*)d_in[4];
    const float* out_w = (const float*)d_in[5];
    const float* out_b = (const float*)d_in[6];
    float* out = (float*)d_out;

    float *xn, *qkv, *sc, *ao;
    cudaGetSymbolAddress((void**)&xn,  g_xn);
    cudaGetSymbolAddress((void**)&qkv, g_qkv);
    cudaGetSymbolAddress((void**)&sc,  g_sc);
    cudaGetSymbolAddress((void**)&ao,  g_ao);

    const size_t sXN  = (size_t)CCH * HW;
    const size_t sQKV = (size_t)3 * CCH * HW;
    const size_t sSC  = (size_t)HW * HW;

    // 1) GroupNorm -> g_xn
    gn_kernel<<<BATCH * NGRP, 256>>>(x, gn_w, gn_b);

    // 2) qkv = W(1536x512) @ xn(512x4096) + b       [per batch]
    {
        dim3 grid(HW / 128, (3 * CCH) / 128, BATCH);
        gemm_kernel<true, false, 1><<<grid, 256>>>(
            qkv_w, xn, qkv, CCH, CCH, HW, HW,
            (size_t)0, sXN, sQKV, 1.f, qkv_b, nullptr, 0);
    }

    // 3) scores[i,j] = scale * sum_c Q[c,i]*K[c,j]
    {
        dim3 grid(HW / 128, HW / 128, BATCH);
        const float scale = 0.044194173824159216f;  // 512^-0.5
        gemm_kernel<false, false, 0><<<grid, 256>>>(
            qkv, qkv + (size_t)CCH * HW, sc, CCH, HW, HW, HW,
            sQKV, sQKV, sSC, scale, nullptr, nullptr, 0);
    }

    // 4) softmax rows
    softmax_kernel<<<BATCH * HW, 256>>>();

    // 5) ao[c,i] = sum_j V[c,j] * P[i,j]
    {
        dim3 grid(HW / 128, CCH / 128, BATCH);
        gemm_kernel<true, true, 0><<<grid, 256>>>(
            qkv + (size_t)2 * CCH * HW, sc, ao, HW, HW, HW, HW,
            sQKV, sSC, sXN, 1.f, nullptr, nullptr, 0);
    }

    // 6) out = OW(512x512) @ ao(512x4096) + out_b + xn
    {
        dim3 grid(HW / 128, CCH / 128, BATCH);
        gemm_kernel<true, false, 3><<<grid, 256>>>(
            out_w, ao, out, CCH, CCH, HW, HW,
            (size_t)0, sXN, sXN, 1.f, out_b, xn, sXN);
    }
}

// round 4
// speedup vs baseline: 2.5371x; 2.5371x over previous
#include <cuda_runtime.h>
#include <cstdint>
#include <math.h>

#define BATCH 4
#define CCH   512
#define HW    4096
#define NGRP  32
#define CPG   16

// ---------------- scratch (device globals; no allocation) ----------------
__device__ float g_xn [(size_t)BATCH * CCH * HW];   // [b][c][i]  32MB
__device__ float g_xnt[(size_t)BATCH * HW * CCH];   // [b][i][c]  32MB
__device__ float g_q  [(size_t)BATCH * HW * CCH];   // [b][i][c]
__device__ float g_k  [(size_t)BATCH * HW * CCH];   // [b][i][c]
__device__ float g_v  [(size_t)BATCH * CCH * HW];   // [b][c][j]
__device__ float g_sc [(size_t)BATCH * HW * HW];    // [b][i][j] 256MB
__device__ float g_ao [(size_t)BATCH * HW * CCH];   // [b][i][c]

// ---------------- helpers ----------------
__device__ __forceinline__ uint32_t smem_u32(const void* p) {
    uint32_t a;
    asm("{ .reg .u64 t; cvta.to.shared.u64 t, %1; cvt.u32.u64 %0, t; }" : "=r"(a) : "l"(p));
    return a;
}
__device__ __forceinline__ void cp_async16(uint32_t s, const void* g) {
    asm volatile("cp.async.cg.shared.global [%0], [%1], 16;" :: "r"(s), "l"(g));
}
#define CP_COMMIT() asm volatile("cp.async.commit_group;" ::: "memory")
#define CP_WAIT(N)  asm volatile("cp.async.wait_group %0;" :: "n"(N) : "memory")

__device__ __forceinline__ uint32_t f2tf32(float f) {
    uint32_t r;
    asm("cvt.rna.tf32.f32 %0, %1;" : "=r"(r) : "f"(f));
    return r;
}

__device__ __forceinline__ void mma_tf32(float* d, const uint32_t* a, const uint32_t* b) {
    asm volatile(
        "mma.sync.aligned.m16n8k8.row.col.f32.tf32.tf32.f32 "
        "{%0,%1,%2,%3}, {%4,%5,%6,%7}, {%8,%9}, {%0,%1,%2,%3};"
        : "+f"(d[0]), "+f"(d[1]), "+f"(d[2]), "+f"(d[3])
        : "r"(a[0]), "r"(a[1]), "r"(a[2]), "r"(a[3]), "r"(b[0]), "r"(b[1]));
}

// ---------------- GroupNorm ----------------
__global__ __launch_bounds__(256) void gn_kernel(const float* __restrict__ x,
                                                 const float* __restrict__ w,
                                                 const float* __restrict__ bias) {
    int bg = blockIdx.x;
    int b = bg / NGRP, g = bg % NGRP;
    const size_t base = ((size_t)(b * CCH + g * CPG)) * HW;
    const float4* x4 = (const float4*)(x + base);
    float4* o4 = (float4*)(g_xn + base);
    int t = threadIdx.x;
    const int N4 = (CPG * HW) / 4;

    float s = 0.f, ss = 0.f;
    for (int i = t; i < N4; i += 256) {
        float4 v = x4[i];
        s  += v.x + v.y + v.z + v.w;
        ss += v.x * v.x + v.y * v.y + v.z * v.z + v.w * v.w;
    }
    __shared__ float sh0[256], sh1[256];
    sh0[t] = s; sh1[t] = ss;
    __syncthreads();
    for (int off = 128; off; off >>= 1) {
        if (t < off) { sh0[t] += sh0[t + off]; sh1[t] += sh1[t + off]; }
        __syncthreads();
    }
    const float inv = 1.f / (float)(CPG * HW);
    float mean = sh0[0] * inv;
    float var  = sh1[0] * inv - mean * mean;
    float rstd = rsqrtf(var + 1e-5f);

    for (int i = t; i < N4; i += 256) {
        int c = g * CPG + ((i * 4) >> 12);
        float sw = w[c] * rstd;
        float sb = bias[c] - mean * sw;
        float4 v = x4[i];
        float4 o;
        o.x = v.x * sw + sb; o.y = v.y * sw + sb;
        o.z = v.z * sw + sb; o.w = v.w * sw + sb;
        o4[i] = o;
    }
}

// ---------------- transpose [C,HW] -> [HW,C] per batch ----------------
__global__ __launch_bounds__(256) void tr_kernel() {
    __shared__ float tile[32][33];
    int b = blockIdx.z;
    const float* in = g_xn + (size_t)b * CCH * HW;
    float* outp = g_xnt + (size_t)b * CCH * HW;
    int i0 = blockIdx.x * 32;
    int c0 = blockIdx.y * 32;
    int tx = threadIdx.x & 31, ty = threadIdx.x >> 5;
#pragma unroll
    for (int j = 0; j < 32; j += 8)
        tile[ty + j][tx] = in[(size_t)(c0 + ty + j) * HW + i0 + tx];
    __syncthreads();
#pragma unroll
    for (int j = 0; j < 32; j += 8)
        outp[(size_t)(i0 + ty + j) * CCH + c0 + tx] = tile[tx][ty + j];
}

// ---------------- tf32 warp-MMA GEMM ----------------
// D[m,n] = alpha * sum_k A[m,k] * B[n,k] (+ epilogue), A/B K-major.
// EPI: 0=scale, 1=+bias[m], 2=+bias[n], 3=+bias[m]+resid[m,n]
// Tile 128x128, K-slab 32, cp.async double buffer, 8 warps (4m x 2n), warp 32x64.
#define LDP 36                      // padded row stride in floats
#define TILE_BYTES (128 * LDP * 4)  // 18432
#define MM_SMEM (4 * TILE_BYTES)    // 73728

template<int EPI>
__global__ __launch_bounds__(256, 2) void mm_kernel(
    const float* __restrict__ A, const float* __restrict__ B, float* __restrict__ C,
    int Kd, int lda, int ldb, int ldc,
    size_t sA, size_t sB, size_t sC,
    float alpha, const float* __restrict__ bias,
    const float* __restrict__ resid, size_t sR)
{
    extern __shared__ float smf[];
    float* As[2] = { smf,                smf + 128 * LDP };
    float* Bs[2] = { smf + 2 * 128 * LDP, smf + 3 * 128 * LDP };
    const uint32_t sbase = smem_u32(smf);

    const int t = threadIdx.x;
    const int lane = t & 31, wid = t >> 5;
    const int gid = lane >> 2, qid = lane & 3;
    const int wm = (wid & 3) * 32, wn = (wid >> 2) * 64;

    const int bz = blockIdx.z;
    const float* Ab = A + (size_t)bz * sA;
    const float* Bb = B + (size_t)bz * sB;
    float* Cb = C + (size_t)bz * sC;
    const int m0 = blockIdx.y * 128;
    const int n0 = blockIdx.x * 128;

    // loader mapping: linear = t + i*256; row = linear>>3; kq = (linear&7)*4
    const int lrow = t >> 3;
    const int lk   = (t & 7) * 4;

    float acc[2][8][4];
#pragma unroll
    for (int mi = 0; mi < 2; mi++)
#pragma unroll
        for (int ni = 0; ni < 8; ni++)
#pragma unroll
            for (int j = 0; j < 4; j++) acc[mi][ni][j] = 0.f;

    const int nslab = Kd >> 5;

    // prefetch slab 0 -> buf 0
    {
        const float* ga = Ab + (size_t)(m0 + lrow) * lda + lk;
        const float* gb = Bb + (size_t)(n0 + lrow) * ldb + lk;
        uint32_t da = sbase + (uint32_t)((lrow * LDP + lk) * 4);
        uint32_t db = da + 2u * TILE_BYTES;
#pragma unroll
        for (int i = 0; i < 4; i++) {
            cp_async16(da + i * 32u * LDP * 4u, ga + (size_t)(i * 32) * lda);
            cp_async16(db + i * 32u * LDP * 4u, gb + (size_t)(i * 32) * ldb);
        }
        CP_COMMIT();
    }

    int buf = 0;
    for (int s = 0; s < nslab; s++) {
        if (s + 1 < nslab) {
            int k0 = (s + 1) << 5;
            int nb = buf ^ 1;
            const float* ga = Ab + (size_t)(m0 + lrow) * lda + k0 + lk;
            const float* gb = Bb + (size_t)(n0 + lrow) * ldb + k0 + lk;
            uint32_t da = sbase + (uint32_t)nb * TILE_BYTES + (uint32_t)((lrow * LDP + lk) * 4);
            uint32_t db = da + 2u * TILE_BYTES;
#pragma unroll
            for (int i = 0; i < 4; i++) {
                cp_async16(da + i * 32u * LDP * 4u, ga + (size_t)(i * 32) * lda);
                cp_async16(db + i * 32u * LDP * 4u, gb + (size_t)(i * 32) * ldb);
            }
            CP_COMMIT();
            CP_WAIT(1);
        } else {
            CP_WAIT(0);
        }
        __syncthreads();

        const float* as = As[buf];
        const float* bs = Bs[buf];
#pragma unroll
        for (int kk = 0; kk < 4; kk++) {
            const int kb = kk * 8;
            uint32_t afr[2][4];
#pragma unroll
            for (int mi = 0; mi < 2; mi++) {
                const float* ap = as + (wm + mi * 16 + gid) * LDP + kb + qid;
                // m16n8k8 tf32 A layout: a0=(g,q) a1=(g+8,q) a2=(g,q+4) a3=(g+8,q+4)
                afr[mi][0] = f2tf32(ap[0]);
                afr[mi][1] = f2tf32(ap[8 * LDP]);
                afr[mi][2] = f2tf32(ap[4]);
                afr[mi][3] = f2tf32(ap[8 * LDP + 4]);
            }
            uint32_t bfr[8][2];
#pragma unroll
            for (int ni = 0; ni < 8; ni++) {
                const float* bp = bs + (wn + ni * 8 + gid) * LDP + kb + qid;
                bfr[ni][0] = f2tf32(bp[0]);
                bfr[ni][1] = f2tf32(bp[4]);
            }
#pragma unroll
            for (int mi = 0; mi < 2; mi++)
#pragma unroll
                for (int ni = 0; ni < 8; ni++)
                    mma_tf32(acc[mi][ni], afr[mi], bfr[ni]);
        }
        __syncthreads();
        buf ^= 1;
    }

    // epilogue
#pragma unroll
    for (int mi = 0; mi < 2; mi++) {
        const int r0 = m0 + wm + mi * 16 + gid;
        const int r1 = r0 + 8;
        float b0 = 0.f, b1 = 0.f;
        if (EPI == 1 || EPI == 3) { b0 = bias[r0]; b1 = bias[r1]; }
#pragma unroll
        for (int ni = 0; ni < 8; ni++) {
            const int col = n0 + wn + ni * 8 + qid * 2;
            float2 o0, o1;
            o0.x = acc[mi][ni][0] * alpha; o0.y = acc[mi][ni][1] * alpha;
            o1.x = acc[mi][ni][2] * alpha; o1.y = acc[mi][ni][3] * alpha;
            if (EPI == 1 || EPI == 3) { o0.x += b0; o0.y += b0; o1.x += b1; o1.y += b1; }
            if (EPI == 2) {
                float bn0 = bias[col], bn1 = bias[col + 1];
                o0.x += bn0; o0.y += bn1; o1.x += bn0; o1.y += bn1;
            }
            if (EPI == 3) {
                const float* rb = resid + (size_t)bz * sR;
                float2 rv0 = *(const float2*)(rb + (size_t)r0 * ldc + col);
                float2 rv1 = *(const float2*)(rb + (size_t)r1 * ldc + col);
                o0.x += rv0.x; o0.y += rv0.y; o1.x += rv1.x; o1.y += rv1.y;
            }
            *(float2*)(Cb + (size_t)r0 * ldc + col) = o0;
            *(float2*)(Cb + (size_t)r1 * ldc + col) = o1;
        }
    }
}

// ---------------- row softmax over g_sc ----------------
__global__ __launch_bounds__(256) void softmax_kernel() {
    float4* row = (float4*)(g_sc + (size_t)blockIdx.x * HW);
    int t = threadIdx.x;
    float4 v[4];
    float mx = -1e30f;
#pragma unroll
    for (int i = 0; i < 4; i++) {
        v[i] = row[t + i * 256];
        mx = fmaxf(mx, fmaxf(fmaxf(v[i].x, v[i].y), fmaxf(v[i].z, v[i].w)));
    }
    __shared__ float sh[8];
#pragma unroll
    for (int o = 16; o; o >>= 1) mx = fmaxf(mx, __shfl_xor_sync(0xffffffffu, mx, o));
    if ((t & 31) == 0) sh[t >> 5] = mx;
    __syncthreads();
    mx = sh[0];
#pragma unroll
    for (int i = 1; i < 8; i++) mx = fmaxf(mx, sh[i]);

    float s = 0.f;
#pragma unroll
    for (int i = 0; i < 4; i++) {
        v[i].x = __expf(v[i].x - mx); v[i].y = __expf(v[i].y - mx);
        v[i].z = __expf(v[i].z - mx); v[i].w = __expf(v[i].w - mx);
        s += v[i].x + v[i].y + v[i].z + v[i].w;
    }
#pragma unroll
    for (int o = 16; o; o >>= 1) s += __shfl_xor_sync(0xffffffffu, s, o);
    __syncthreads();
    if ((t & 31) == 0) sh[t >> 5] = s;
    __syncthreads();
    s = 0.f;
#pragma unroll
    for (int i = 0; i < 8; i++) s += sh[i];
    float inv = 1.f / s;
#pragma unroll
    for (int i = 0; i < 4; i++) {
        v[i].x *= inv; v[i].y *= inv; v[i].z *= inv; v[i].w *= inv;
        row[t + i * 256] = v[i];
    }
}

// ---------------- launch ----------------
extern "C" void kernel_launch(void* const* d_in, const int* in_sizes, int n_in,
                              void* d_out, int out_size) {
    const float* x     = (const float*)d_in[0];
    const float* gn_w  = (const float*)d_in[1];
    const float* gn_b  = (const float*)d_in[2];
    const float* qkv_w = (const float*)d_in[3];
    const float* qkv_b = (const float*)d_in[4];
    const float* out_w = (const float*)d_in[5];
    const float* out_b = (const float*)d_in[6];
    float* out = (float*)d_out;

    float *xn, *xnt, *q, *k, *v, *sc, *ao;
    cudaGetSymbolAddress((void**)&xn,  g_xn);
    cudaGetSymbolAddress((void**)&xnt, g_xnt);
    cudaGetSymbolAddress((void**)&q,   g_q);
    cudaGetSymbolAddress((void**)&k,   g_k);
    cudaGetSymbolAddress((void**)&v,   g_v);
    cudaGetSymbolAddress((void**)&sc,  g_sc);
    cudaGetSymbolAddress((void**)&ao,  g_ao);

    cudaFuncSetAttribute(mm_kernel<0>, cudaFuncAttributeMaxDynamicSharedMemorySize, MM_SMEM);
    cudaFuncSetAttribute(mm_kernel<1>, cudaFuncAttributeMaxDynamicSharedMemorySize, MM_SMEM);
    cudaFuncSetAttribute(mm_kernel<2>, cudaFuncAttributeMaxDynamicSharedMemorySize, MM_SMEM);
    cudaFuncSetAttribute(mm_kernel<3>, cudaFuncAttributeMaxDynamicSharedMemorySize, MM_SMEM);

    const size_t sXN = (size_t)CCH * HW;
    const size_t sSC = (size_t)HW * HW;

    // 1) GroupNorm -> g_xn [C, HW]
    gn_kernel<<<BATCH * NGRP, 256>>>(x, gn_w, gn_b);
    // 2) transpose -> g_xnt [HW, C]
    tr_kernel<<<dim3(HW / 32, CCH / 32, BATCH), 256>>>();

    // 3) Q[i,o] = xnt[i,:] . Wq[o,:] + qkv_b[o]
    mm_kernel<2><<<dim3(CCH / 128, HW / 128, BATCH), 256, MM_SMEM>>>(
        xnt, qkv_w, q, CCH, CCH, CCH, CCH, sXN, 0, sXN, 1.f, qkv_b, nullptr, 0);
    // 4) K[i,o]
    mm_kernel<2><<<dim3(CCH / 128, HW / 128, BATCH), 256, MM_SMEM>>>(
        xnt, qkv_w + (size_t)CCH * CCH, k, CCH, CCH, CCH, CCH, sXN, 0, sXN, 1.f,
        qkv_b + CCH, nullptr, 0);
    // 5) V[o,j] = Wv[o,:] . xnt[j,:] + qkv_b[o]
    mm_kernel<1><<<dim3(HW / 128, CCH / 128, BATCH), 256, MM_SMEM>>>(
        qkv_w + (size_t)2 * CCH * CCH, xnt, v, CCH, CCH, CCH, HW, 0, sXN, sXN, 1.f,
        qkv_b + 2 * CCH, nullptr, 0);

    // 6) scores[i,j] = scale * Q[i,:].K[j,:]
    mm_kernel<0><<<dim3(HW / 128, HW / 128, BATCH), 256, MM_SMEM>>>(
        q, k, sc, CCH, CCH, CCH, HW, sXN, sXN, sSC,
        0.044194173824159216f, nullptr, nullptr, 0);

    // 7) softmax rows
    softmax_kernel<<<BATCH * HW, 256>>>();

    // 8) ao[i,c] = P[i,:] . V[c,:]
    mm_kernel<0><<<dim3(CCH / 128, HW / 128, BATCH), 256, MM_SMEM>>>(
        sc, v, ao, HW, HW, HW, CCH, sSC, sXN, sXN, 1.f, nullptr, nullptr, 0);

    // 9) out[o,i] = OW[o,:] . ao[i,:] + out_b[o] + xn[o,i]
    mm_kernel<3><<<dim3(HW / 128, CCH / 128, BATCH), 256, MM_SMEM>>>(
        out_w, ao, out, CCH, CCH, CCH, HW, 0, sXN, sXN, 1.f, out_b, xn, sXN);
}

// round 6
// speedup vs baseline: 2.6753x; 1.0545x over previous
#include <cuda_runtime.h>
#include <cstdint>
#include <math.h>

#define BATCH 4
#define CCH   512
#define HW    4096
#define NGRP  32
#define CPG   16

// ---------------- scratch (device globals; no allocation) ----------------
__device__ float g_xn [(size_t)BATCH * CCH * HW];   // [b][c][i]  residual, fp32, unpermuted
__device__ float g_xnt[(size_t)BATCH * HW * CCH];   // [b][i][c'] tf32-rounded, k-permuted
__device__ float g_q  [(size_t)BATCH * HW * CCH];   // [b][i][c']
__device__ float g_k  [(size_t)BATCH * HW * CCH];   // [b][i][c']
__device__ float g_v  [(size_t)BATCH * CCH * HW];   // [b][c][j']
__device__ float g_sc [(size_t)BATCH * HW * HW];    // [b][i][j'] 256MB
__device__ float g_ao [(size_t)BATCH * HW * CCH];   // [b][i][c']
__device__ float g_wq [(size_t)3 * CCH * CCH];      // rounded+permuted qkv_w
__device__ float g_wo [(size_t)CCH * CCH];          // rounded+permuted out_w

// ---------------- helpers ----------------
__device__ __forceinline__ uint32_t smem_u32(const void* p) {
    uint32_t a;
    asm("{ .reg .u64 t; cvta.to.shared.u64 t, %1; cvt.u32.u64 %0, t; }" : "=r"(a) : "l"(p));
    return a;
}
__device__ __forceinline__ void cp_async16(uint32_t s, const void* g) {
    asm volatile("cp.async.cg.shared.global [%0], [%1], 16;" :: "r"(s), "l"(g));
}
#define CP_COMMIT() asm volatile("cp.async.commit_group;" ::: "memory")
#define CP_WAIT(N)  asm volatile("cp.async.wait_group %0;" :: "n"(N) : "memory")

__device__ __forceinline__ float rtf(float f) {   // round fp32 -> tf32 value
    uint32_t r;
    asm("cvt.rna.tf32.f32 %0, %1;" : "=r"(r) : "f"(f));
    return __uint_as_float(r);
}
__device__ __forceinline__ int perm8(int j) { return ((j & 3) << 1) | ((j >> 2) & 1); }

__device__ __forceinline__ void mma_tf32(float* d, const uint32_t* a, const uint32_t* b) {
    asm volatile(
        "mma.sync.aligned.m16n8k8.row.col.f32.tf32.tf32.f32 "
        "{%0,%1,%2,%3}, {%4,%5,%6,%7}, {%8,%9}, {%0,%1,%2,%3};"
        : "+f"(d[0]), "+f"(d[1]), "+f"(d[2]), "+f"(d[3])
        : "r"(a[0]), "r"(a[1]), "r"(a[2]), "r"(a[3]), "r"(b[0]), "r"(b[1]));
}

// ---------------- weight prep: round + k-permute cols (512 cols) ----------------
__global__ __launch_bounds__(256) void prep_w_kernel(const float* __restrict__ src,
                                                     float* __restrict__ dst, int n) {
    int i = blockIdx.x * 256 + threadIdx.x;
    if (i < n) {
        int col = i & 511;
        int row = i >> 9;
        int c2 = (col & ~7) | perm8(col & 7);
        dst[(size_t)row * 512 + c2] = rtf(src[i]);
    }
}

// ---------------- GroupNorm ----------------
__global__ __launch_bounds__(256) void gn_kernel(const float* __restrict__ x,
                                                 const float* __restrict__ w,
                                                 const float* __restrict__ bias) {
    int bg = blockIdx.x;
    int b = bg / NGRP, g = bg % NGRP;
    const size_t base = ((size_t)(b * CCH + g * CPG)) * HW;
    const float4* x4 = (const float4*)(x + base);
    float4* o4 = (float4*)(g_xn + base);
    int t = threadIdx.x;
    const int N4 = (CPG * HW) / 4;

    float s = 0.f, ss = 0.f;
    for (int i = t; i < N4; i += 256) {
        float4 v = x4[i];
        s  += v.x + v.y + v.z + v.w;
        ss += v.x * v.x + v.y * v.y + v.z * v.z + v.w * v.w;
    }
    __shared__ float sh0[256], sh1[256];
    sh0[t] = s; sh1[t] = ss;
    __syncthreads();
    for (int off = 128; off; off >>= 1) {
        if (t < off) { sh0[t] += sh0[t + off]; sh1[t] += sh1[t + off]; }
        __syncthreads();
    }
    const float inv = 1.f / (float)(CPG * HW);
    float mean = sh0[0] * inv;
    float var  = sh1[0] * inv - mean * mean;
    float rstd = rsqrtf(var + 1e-5f);

    for (int i = t; i < N4; i += 256) {
        int c = g * CPG + ((i * 4) >> 12);
        float sw = w[c] * rstd;
        float sb = bias[c] - mean * sw;
        float4 v = x4[i];
        float4 o;
        o.x = v.x * sw + sb; o.y = v.y * sw + sb;
        o.z = v.z * sw + sb; o.w = v.w * sw + sb;
        o4[i] = o;
    }
}

// ---------------- transpose [C,HW] -> [HW,C'] (round + permute cols) ----------------
__global__ __launch_bounds__(256) void tr_kernel() {
    __shared__ float tile[32][33];
    int b = blockIdx.z;
    const float* in = g_xn + (size_t)b * CCH * HW;
    float* outp = g_xnt + (size_t)b * CCH * HW;
    int i0 = blockIdx.x * 32;
    int c0 = blockIdx.y * 32;
    int tx = threadIdx.x & 31, ty = threadIdx.x >> 5;
#pragma unroll
    for (int j = 0; j < 32; j += 8)
        tile[ty + j][tx] = in[(size_t)(c0 + ty + j) * HW + i0 + tx];
    __syncthreads();
    const int cperm = c0 + (tx & ~7) + perm8(tx & 7);
#pragma unroll
    for (int j = 0; j < 32; j += 8)
        outp[(size_t)(i0 + ty + j) * CCH + cperm] = rtf(tile[tx][ty + j]);
}

// ---------------- tf32 warp-MMA GEMM ----------------
// D[m,n] = alpha * sum_k A[m,k] * B[n,k] (+ epilogue).
// Operands are pre-rounded to tf32 and k-permuted (perm8 within 8-blocks).
// EPI: 0=scale, 1=+bias[m], 2=+bias[n], 3=+bias[m]+resid[m,n]
// PERM: permute output cols (output feeds another GEMM's k). ROUND: round output to tf32.
// Tile 128x128, K-slab 32, cp.async double buffer, 8 warps (4m x 2n), warp 32x64.
#define LDP 36
#define TILE_BYTES (128 * LDP * 4)  // 18432
#define MM_SMEM (4 * TILE_BYTES)    // 73728

template<int EPI, int PERM, int ROUND>
__global__ __launch_bounds__(256, 2) void mm_kernel(
    const float* __restrict__ A, const float* __restrict__ B, float* __restrict__ C,
    int Kd, int lda, int ldb, int ldc,
    size_t sA, size_t sB, size_t sC,
    float alpha, const float* __restrict__ bias,
    const float* __restrict__ resid, size_t sR)
{
    extern __shared__ float smf[];
    float* As[2] = { smf,                 smf + 128 * LDP };
    float* Bs[2] = { smf + 2 * 128 * LDP, smf + 3 * 128 * LDP };
    const uint32_t sbase = smem_u32(smf);

    const int t = threadIdx.x;
    const int lane = t & 31, wid = t >> 5;
    const int gid = lane >> 2, qid = lane & 3;
    const int wm = (wid & 3) * 32, wn = (wid >> 2) * 64;

    const int bz = blockIdx.z;
    const float* Ab = A + (size_t)bz * sA;
    const float* Bb = B + (size_t)bz * sB;
    float* Cb = C + (size_t)bz * sC;
    const int m0 = blockIdx.y * 128;
    const int n0 = blockIdx.x * 128;

    const int lrow = t >> 3;
    const int lk   = (t & 7) * 4;

    float acc[2][8][4];
#pragma unroll
    for (int mi = 0; mi < 2; mi++)
#pragma unroll
        for (int ni = 0; ni < 8; ni++)
#pragma unroll
            for (int j = 0; j < 4; j++) acc[mi][ni][j] = 0.f;

    const int nslab = Kd >> 5;

    {
        const float* ga = Ab + (size_t)(m0 + lrow) * lda + lk;
        const float* gb = Bb + (size_t)(n0 + lrow) * ldb + lk;
        uint32_t da = sbase + (uint32_t)((lrow * LDP + lk) * 4);
        uint32_t db = da + 2u * TILE_BYTES;
#pragma unroll
        for (int i = 0; i < 4; i++) {
            cp_async16(da + i * 32u * LDP * 4u, ga + (size_t)(i * 32) * lda);
            cp_async16(db + i * 32u * LDP * 4u, gb + (size_t)(i * 32) * ldb);
        }
        CP_COMMIT();
    }

    int buf = 0;
    for (int s = 0; s < nslab; s++) {
        if (s + 1 < nslab) {
            int k0 = (s + 1) << 5;
            int nb = buf ^ 1;
            const float* ga = Ab + (size_t)(m0 + lrow) * lda + k0 + lk;
            const float* gb = Bb + (size_t)(n0 + lrow) * ldb + k0 + lk;
            uint32_t da = sbase + (uint32_t)nb * TILE_BYTES + (uint32_t)((lrow * LDP + lk) * 4);
            uint32_t db = da + 2u * TILE_BYTES;
#pragma unroll
            for (int i = 0; i < 4; i++) {
                cp_async16(da + i * 32u * LDP * 4u, ga + (size_t)(i * 32) * lda);
                cp_async16(db + i * 32u * LDP * 4u, gb + (size_t)(i * 32) * ldb);
            }
            CP_COMMIT();
            CP_WAIT(1);
        } else {
            CP_WAIT(0);
        }
        __syncthreads();

        const float* as = As[buf];
        const float* bs = Bs[buf];
#pragma unroll
        for (int kk = 0; kk < 4; kk++) {
            const int kb = kk * 8;
            // permuted layout: (k=q, k=q+4) adjacent at offset kb + 2q
            uint32_t afr[2][4];
#pragma unroll
            for (int mi = 0; mi < 2; mi++) {
                const float* ap = as + (wm + mi * 16 + gid) * LDP + kb + 2 * qid;
                float2 va = *(const float2*)ap;             // (g,   q), (g,   q+4)
                float2 vb = *(const float2*)(ap + 8 * LDP); // (g+8, q), (g+8, q+4)
                afr[mi][0] = __float_as_uint(va.x);
                afr[mi][1] = __float_as_uint(vb.x);
                afr[mi][2] = __float_as_uint(va.y);
                afr[mi][3] = __float_as_uint(vb.y);
            }
            uint32_t bfr[8][2];
#pragma unroll
            for (int ni = 0; ni < 8; ni++) {
                float2 vb = *(const float2*)(bs + (wn + ni * 8 + gid) * LDP + kb + 2 * qid);
                bfr[ni][0] = __float_as_uint(vb.x);
                bfr[ni][1] = __float_as_uint(vb.y);
            }
#pragma unroll
            for (int mi = 0; mi < 2; mi++)
#pragma unroll
                for (int ni = 0; ni < 8; ni++)
                    mma_tf32(acc[mi][ni], afr[mi], bfr[ni]);
        }
        __syncthreads();
        buf ^= 1;
    }

    // epilogue
    const int j0 = qid * 2, j1 = qid * 2 + 1;
    const int p0 = PERM ? perm8(j0) : j0;
    const int p1 = PERM ? perm8(j1) : j1;
#pragma unroll
    for (int mi = 0; mi < 2; mi++) {
        const int r0 = m0 + wm + mi * 16 + gid;
        const int r1 = r0 + 8;
        float b0 = 0.f, b1 = 0.f;
        if (EPI == 1 || EPI == 3) { b0 = bias[r0]; b1 = bias[r1]; }
#pragma unroll
        for (int ni = 0; ni < 8; ni++) {
            const int colb = n0 + wn + ni * 8;
            float o00 = acc[mi][ni][0] * alpha, o01 = acc[mi][ni][1] * alpha;
            float o10 = acc[mi][ni][2] * alpha, o11 = acc[mi][ni][3] * alpha;
            if (EPI == 1 || EPI == 3) { o00 += b0; o01 += b0; o10 += b1; o11 += b1; }
            if (EPI == 2) {
                float bn0 = bias[colb + j0], bn1 = bias[colb + j1];
                o00 += bn0; o01 += bn1; o10 += bn0; o11 += bn1;
            }
            if (EPI == 3) {
                const float* rb = resid + (size_t)bz * sR;
                o00 += rb[(size_t)r0 * ldc + colb + j0];
                o01 += rb[(size_t)r0 * ldc + colb + j1];
                o10 += rb[(size_t)r1 * ldc + colb + j0];
                o11 += rb[(size_t)r1 * ldc + colb + j1];
            }
            if (ROUND) { o00 = rtf(o00); o01 = rtf(o01); o10 = rtf(o10); o11 = rtf(o11); }
            Cb[(size_t)r0 * ldc + colb + p0] = o00;
            Cb[(size_t)r0 * ldc + colb + p1] = o01;
            Cb[(size_t)r1 * ldc + colb + p0] = o10;
            Cb[(size_t)r1 * ldc + colb + p1] = o11;
        }
    }
}

// ---------------- row softmax over g_sc (rows already k-permuted; order-invariant) ----------------
__global__ __launch_bounds__(256) void softmax_kernel() {
    float4* row = (float4*)(g_sc + (size_t)blockIdx.x * HW);
    int t = threadIdx.x;
    float4 v[4];
    float mx = -1e30f;
#pragma unroll
    for (int i = 0; i < 4; i++) {
        v[i] = row[t + i * 256];
        mx = fmaxf(mx, fmaxf(fmaxf(v[i].x, v[i].y), fmaxf(v[i].z, v[i].w)));
    }
    __shared__ float sh[8];
#pragma unroll
    for (int o = 16; o; o >>= 1) mx = fmaxf(mx, __shfl_xor_sync(0xffffffffu, mx, o));
    if ((t & 31) == 0) sh[t >> 5] = mx;
    __syncthreads();
    mx = sh[0];
#pragma unroll
    for (int i = 1; i < 8; i++) mx = fmaxf(mx, sh[i]);

    float s = 0.f;
#pragma unroll
    for (int i = 0; i < 4; i++) {
        v[i].x = __expf(v[i].x - mx); v[i].y = __expf(v[i].y - mx);
        v[i].z = __expf(v[i].z - mx); v[i].w = __expf(v[i].w - mx);
        s += v[i].x + v[i].y + v[i].z + v[i].w;
    }
#pragma unroll
    for (int o = 16; o; o >>= 1) s += __shfl_xor_sync(0xffffffffu, s, o);
    __syncthreads();
    if ((t & 31) == 0) sh[t >> 5] = s;
    __syncthreads();
    s = 0.f;
#pragma unroll
    for (int i = 0; i < 8; i++) s += sh[i];
    float inv = 1.f / s;
#pragma unroll
    for (int i = 0; i < 4; i++) {
        v[i].x = rtf(v[i].x * inv); v[i].y = rtf(v[i].y * inv);
        v[i].z = rtf(v[i].z * inv); v[i].w = rtf(v[i].w * inv);
        row[t + i * 256] = v[i];
    }
}

// ---------------- launch ----------------
extern "C" void kernel_launch(void* const* d_in, const int* in_sizes, int n_in,
                              void* d_out, int out_size) {
    const float* x     = (const float*)d_in[0];
    const float* gn_w  = (const float*)d_in[1];
    const float* gn_b  = (const float*)d_in[2];
    const float* qkv_w = (const float*)d_in[3];
    const float* qkv_b = (const float*)d_in[4];
    const float* out_w = (const float*)d_in[5];
    const float* out_b = (const float*)d_in[6];
    float* out = (float*)d_out;

    float *xn, *xnt, *q, *k, *v, *sc, *ao, *wq, *wo;
    cudaGetSymbolAddress((void**)&xn,  g_xn);
    cudaGetSymbolAddress((void**)&xnt, g_xnt);
    cudaGetSymbolAddress((void**)&q,   g_q);
    cudaGetSymbolAddress((void**)&k,   g_k);
    cudaGetSymbolAddress((void**)&v,   g_v);
    cudaGetSymbolAddress((void**)&sc,  g_sc);
    cudaGetSymbolAddress((void**)&ao,  g_ao);
    cudaGetSymbolAddress((void**)&wq,  g_wq);
    cudaGetSymbolAddress((void**)&wo,  g_wo);

    cudaFuncSetAttribute(mm_kernel<0,1,0>, cudaFuncAttributeMaxDynamicSharedMemorySize, MM_SMEM);
    cudaFuncSetAttribute(mm_kernel<0,1,1>, cudaFuncAttributeMaxDynamicSharedMemorySize, MM_SMEM);
    cudaFuncSetAttribute(mm_kernel<1,1,1>, cudaFuncAttributeMaxDynamicSharedMemorySize, MM_SMEM);
    cudaFuncSetAttribute(mm_kernel<2,1,1>, cudaFuncAttributeMaxDynamicSharedMemorySize, MM_SMEM);
    cudaFuncSetAttribute(mm_kernel<3,0,0>, cudaFuncAttributeMaxDynamicSharedMemorySize, MM_SMEM);

    const size_t sXN = (size_t)CCH * HW;
    const size_t sSC = (size_t)HW * HW;

    // 0) weight prep (round + permute)
    prep_w_kernel<<<(3 * CCH * CCH + 255) / 256, 256>>>(qkv_w, wq, 3 * CCH * CCH);
    prep_w_kernel<<<(CCH * CCH + 255) / 256, 256>>>(out_w, wo, CCH * CCH);

    // 1) GroupNorm -> g_xn [C, HW]
    gn_kernel<<<BATCH * NGRP, 256>>>(x, gn_w, gn_b);
    // 2) transpose -> g_xnt [HW, C'] (rounded, permuted)
    tr_kernel<<<dim3(HW / 32, CCH / 32, BATCH), 256>>>();

    // 3) Q[i,o'] = xnt[i,:] . Wq[o,:] + qkv_b[o]
    mm_kernel<2,1,1><<<dim3(CCH / 128, HW / 128, BATCH), 256, MM_SMEM>>>(
        xnt, wq, q, CCH, CCH, CCH, CCH, sXN, 0, sXN, 1.f, qkv_b, nullptr, 0);
    // 4) K[i,o']
    mm_kernel<2,1,1><<<dim3(CCH / 128, HW / 128, BATCH), 256, MM_SMEM>>>(
        xnt, wq + (size_t)CCH * CCH, k, CCH, CCH, CCH, CCH, sXN, 0, sXN, 1.f,
        qkv_b + CCH, nullptr, 0);
    // 5) V[o,j'] = Wv[o,:] . xnt[j,:] + qkv_b[o]
    mm_kernel<1,1,1><<<dim3(HW / 128, CCH / 128, BATCH), 256, MM_SMEM>>>(
        wq + (size_t)2 * CCH * CCH, xnt, v, CCH, CCH, CCH, HW, 0, sXN, sXN, 1.f,
        qkv_b + 2 * CCH, nullptr, 0);

    // 6) scores[i,j'] = scale * Q[i,:].K[j,:]
    mm_kernel<0,1,0><<<dim3(HW / 128, HW / 128, BATCH), 256, MM_SMEM>>>(
        q, k, sc, CCH, CCH, CCH, HW, sXN, sXN, sSC,
        0.044194173824159216f, nullptr, nullptr, 0);

    // 7) softmax rows (rounds P to tf32 on write)
    softmax_kernel<<<BATCH * HW, 256>>>();

    // 8) ao[i,c'] = P[i,:] . V[c,:]
    mm_kernel<0,1,1><<<dim3(CCH / 128, HW / 128, BATCH), 256, MM_SMEM>>>(
        sc, v, ao, HW, HW, HW, CCH, sSC, sXN, sXN, 1.f, nullptr, nullptr, 0);

    // 9) out[o,i] = OW[o,:] . ao[i,:] + out_b[o] + xn[o,i]
    mm_kernel<3,0,0><<<dim3(HW / 128, CCH / 128, BATCH), 256, MM_SMEM>>>(
        wo, ao, out, CCH, CCH, CCH, HW, 0, sXN, sXN, 1.f, out_b, xn, sXN);
}

// round 8
// speedup vs baseline: 3.1621x; 1.1820x over previous
#include <cuda_runtime.h>
#include <cuda_bf16.h>
#include <cstdint>
#include <math.h>

#define BATCH 4
#define CCH   512
#define HW    4096
#define NGRP  32
#define CPG   16

// ---------------- scratch (device globals; no allocation) ----------------
__device__ float g_xn [(size_t)BATCH * CCH * HW];          // residual fp32 [b][c][i]
__device__ float g_xnt[(size_t)BATCH * HW * CCH];          // tf32, elem-perm [b][i][c']
__device__ __nv_bfloat16 g_xnb[(size_t)BATCH * HW * CCH];  // bf16, pair-perm [b][i][c'']
__device__ float g_q  [(size_t)BATCH * HW * CCH];          // tf32 [b][i][o']
__device__ float g_k  [(size_t)BATCH * HW * CCH];          // tf32 [b][i][o']
__device__ __nv_bfloat16 g_v [(size_t)BATCH * CCH * HW];   // bf16 [b][c][j'']
__device__ float g_sc [(size_t)BATCH * HW * HW];           // fp32 scores [b][i][j''] 256MB
__device__ __nv_bfloat16 g_p [(size_t)BATCH * HW * HW];    // bf16 probs  [b][i][j''] 128MB
__device__ __nv_bfloat16 g_ao[(size_t)BATCH * HW * CCH];   // bf16 [b][i][c'']
__device__ float g_wq [(size_t)2 * CCH * CCH];             // tf32 elem-perm Wq,Wk
__device__ __nv_bfloat16 g_wvb[(size_t)CCH * CCH];         // bf16 pair-perm Wv
__device__ __nv_bfloat16 g_wob[(size_t)CCH * CCH];         // bf16 pair-perm Wo

// ---------------- helpers ----------------
__device__ __forceinline__ uint32_t smem_u32(const void* p) {
    uint32_t a;
    asm("{ .reg .u64 t; cvta.to.shared.u64 t, %1; cvt.u32.u64 %0, t; }" : "=r"(a) : "l"(p));
    return a;
}
__device__ __forceinline__ void cp_async16(uint32_t s, const void* g) {
    asm volatile("cp.async.cg.shared.global [%0], [%1], 16;" :: "r"(s), "l"(g));
}
#define CP_COMMIT() asm volatile("cp.async.commit_group;" ::: "memory")
#define CP_WAIT(N)  asm volatile("cp.async.wait_group %0;" :: "n"(N) : "memory")

__device__ __forceinline__ float rtf(float f) {
    uint32_t r;
    asm("cvt.rna.tf32.f32 %0, %1;" : "=r"(r) : "f"(f));
    return __uint_as_float(r);
}
__device__ __forceinline__ int perm8(int j) { return ((j & 3) << 1) | ((j >> 2) & 1); }
__device__ __forceinline__ int permbf(int c) {  // bf16 pair permutation within 16-blocks
    return (c & ~15) | (perm8((c >> 1) & 7) << 1) | (c & 1);
}
__device__ __forceinline__ int permpair(int pi) {  // pair-index version
    return (pi & ~7) | perm8(pi & 7);
}
__device__ __forceinline__ uint32_t pack_bf2(float lo, float hi) {
    __nv_bfloat162 h = __floats2bfloat162_rn(lo, hi);
    return *reinterpret_cast<uint32_t*>(&h);
}

__device__ __forceinline__ void mma_tf32(float* d, const uint32_t* a, const uint32_t* b) {
    asm volatile(
        "mma.sync.aligned.m16n8k8.row.col.f32.tf32.tf32.f32 "
        "{%0,%1,%2,%3}, {%4,%5,%6,%7}, {%8,%9}, {%0,%1,%2,%3};"
        : "+f"(d[0]), "+f"(d[1]), "+f"(d[2]), "+f"(d[3])
        : "r"(a[0]), "r"(a[1]), "r"(a[2]), "r"(a[3]), "r"(b[0]), "r"(b[1]));
}
__device__ __forceinline__ void mma_bf16(float* d, uint32_t a0, uint32_t a1, uint32_t a2,
                                         uint32_t a3, uint32_t b0, uint32_t b1) {
    asm volatile(
        "mma.sync.aligned.m16n8k16.row.col.f32.bf16.bf16.f32 "
        "{%0,%1,%2,%3}, {%4,%5,%6,%7}, {%8,%9}, {%0,%1,%2,%3};"
        : "+f"(d[0]), "+f"(d[1]), "+f"(d[2]), "+f"(d[3])
        : "r"(a0), "r"(a1), "r"(a2), "r"(a3), "r"(b0), "r"(b1));
}

// ---------------- weight prep ----------------
__global__ __launch_bounds__(256) void prep_w_kernel(const float* __restrict__ src,
                                                     float* __restrict__ dst, int n) {
    int i = blockIdx.x * 256 + threadIdx.x;
    if (i < n) {
        int col = i & 511, row = i >> 9;
        int c2 = (col & ~7) | perm8(col & 7);
        dst[(size_t)row * 512 + c2] = rtf(src[i]);
    }
}
__global__ __launch_bounds__(256) void prep_wb_kernel(const float* __restrict__ src,
                                                      __nv_bfloat16* __restrict__ dst, int n) {
    int i = blockIdx.x * 256 + threadIdx.x;
    if (i < n) {
        int col = i & 511, row = i >> 9;
        dst[(size_t)row * 512 + permbf(col)] = __float2bfloat16_rn(src[i]);
    }
}

// ---------------- GroupNorm ----------------
__global__ __launch_bounds__(256) void gn_kernel(const float* __restrict__ x,
                                                 const float* __restrict__ w,
                                                 const float* __restrict__ bias) {
    int bg = blockIdx.x;
    int b = bg / NGRP, g = bg % NGRP;
    const size_t base = ((size_t)(b * CCH + g * CPG)) * HW;
    const float4* x4 = (const float4*)(x + base);
    float4* o4 = (float4*)(g_xn + base);
    int t = threadIdx.x;
    const int N4 = (CPG * HW) / 4;

    float s = 0.f, ss = 0.f;
    for (int i = t; i < N4; i += 256) {
        float4 v = x4[i];
        s  += v.x + v.y + v.z + v.w;
        ss += v.x * v.x + v.y * v.y + v.z * v.z + v.w * v.w;
    }
    __shared__ float sh0[256], sh1[256];
    sh0[t] = s; sh1[t] = ss;
    __syncthreads();
    for (int off = 128; off; off >>= 1) {
        if (t < off) { sh0[t] += sh0[t + off]; sh1[t] += sh1[t + off]; }
        __syncthreads();
    }
    const float inv = 1.f / (float)(CPG * HW);
    float mean = sh0[0] * inv;
    float var  = sh1[0] * inv - mean * mean;
    float rstd = rsqrtf(var + 1e-5f);

    for (int i = t; i < N4; i += 256) {
        int c = g * CPG + ((i * 4) >> 12);
        float sw = w[c] * rstd;
        float sb = bias[c] - mean * sw;
        float4 v = x4[i];
        float4 o;
        o.x = v.x * sw + sb; o.y = v.y * sw + sb;
        o.z = v.z * sw + sb; o.w = v.w * sw + sb;
        o4[i] = o;
    }
}

// ---------------- transpose -> xnt (tf32 elem-perm) + xnb (bf16 pair-perm) ----------------
__global__ __launch_bounds__(256) void tr_kernel() {
    __shared__ float tile[32][33];
    int b = blockIdx.z;
    const float* in = g_xn + (size_t)b * CCH * HW;
    float* ot = g_xnt + (size_t)b * CCH * HW;
    __nv_bfloat16* ob = g_xnb + (size_t)b * CCH * HW;
    int i0 = blockIdx.x * 32;
    int c0 = blockIdx.y * 32;
    int tx = threadIdx.x & 31, ty = threadIdx.x >> 5;
#pragma unroll
    for (int j = 0; j < 32; j += 8)
        tile[ty + j][tx] = in[(size_t)(c0 + ty + j) * HW + i0 + tx];
    __syncthreads();
    const int c = c0 + tx;
    const int ct = c0 + ((tx & ~7) | perm8(tx & 7));
    const int cb = permbf(c);
#pragma unroll
    for (int j = 0; j < 32; j += 8) {
        float f = tile[tx][ty + j];
        ot[(size_t)(i0 + ty + j) * CCH + ct] = rtf(f);
        ob[(size_t)(i0 + ty + j) * CCH + cb] = __float2bfloat16_rn(f);
    }
}

// ---------------- tf32 warp-MMA GEMM (Q, K, scores) ----------------
// PERM: 1 = element perm8 (out feeds tf32 GEMM k), 2 = bf16-pair positions (out feeds bf16 k)
#define LDP 36
#define TILE_BYTES (128 * LDP * 4)
#define MM_SMEM (4 * TILE_BYTES)

template<int EPI, int PERM, int ROUND>
__global__ __launch_bounds__(256, 2) void mm_kernel(
    const float* __restrict__ A, const float* __restrict__ B, float* __restrict__ C,
    int Kd, int lda, int ldb, int ldc,
    size_t sA, size_t sB, size_t sC,
    float alpha, const float* __restrict__ bias)
{
    extern __shared__ float smf[];
    float* As[2] = { smf,                 smf + 128 * LDP };
    float* Bs[2] = { smf + 2 * 128 * LDP, smf + 3 * 128 * LDP };
    const uint32_t sbase = smem_u32(smf);

    const int t = threadIdx.x;
    const int lane = t & 31, wid = t >> 5;
    const int gid = lane >> 2, qid = lane & 3;
    const int wm = (wid & 3) * 32, wn = (wid >> 2) * 64;

    const int bz = blockIdx.z;
    const float* Ab = A + (size_t)bz * sA;
    const float* Bb = B + (size_t)bz * sB;
    float* Cb = C + (size_t)bz * sC;
    const int m0 = blockIdx.y * 128;
    const int n0 = blockIdx.x * 128;

    const int lrow = t >> 3;
    const int lk   = (t & 7) * 4;

    float acc[2][8][4];
#pragma unroll
    for (int mi = 0; mi < 2; mi++)
#pragma unroll
        for (int ni = 0; ni < 8; ni++)
#pragma unroll
            for (int j = 0; j < 4; j++) acc[mi][ni][j] = 0.f;

    const int nslab = Kd >> 5;

    {
        const float* ga = Ab + (size_t)(m0 + lrow) * lda + lk;
        const float* gb = Bb + (size_t)(n0 + lrow) * ldb + lk;
        uint32_t da = sbase + (uint32_t)((lrow * LDP + lk) * 4);
        uint32_t db = da + 2u * TILE_BYTES;
#pragma unroll
        for (int i = 0; i < 4; i++) {
            cp_async16(da + i * 32u * LDP * 4u, ga + (size_t)(i * 32) * lda);
            cp_async16(db + i * 32u * LDP * 4u, gb + (size_t)(i * 32) * ldb);
        }
        CP_COMMIT();
    }

    int buf = 0;
    for (int s = 0; s < nslab; s++) {
        if (s + 1 < nslab) {
            int k0 = (s + 1) << 5;
            int nb = buf ^ 1;
            const float* ga = Ab + (size_t)(m0 + lrow) * lda + k0 + lk;
            const float* gb = Bb + (size_t)(n0 + lrow) * ldb + k0 + lk;
            uint32_t da = sbase + (uint32_t)nb * TILE_BYTES + (uint32_t)((lrow * LDP + lk) * 4);
            uint32_t db = da + 2u * TILE_BYTES;
#pragma unroll
            for (int i = 0; i < 4; i++) {
                cp_async16(da + i * 32u * LDP * 4u, ga + (size_t)(i * 32) * lda);
                cp_async16(db + i * 32u * LDP * 4u, gb + (size_t)(i * 32) * ldb);
            }
            CP_COMMIT();
            CP_WAIT(1);
        } else {
            CP_WAIT(0);
        }
        __syncthreads();

        const float* as = As[buf];
        const float* bs = Bs[buf];
#pragma unroll
        for (int kk = 0; kk < 4; kk++) {
            const int kb = kk * 8;
            uint32_t afr[2][4];
#pragma unroll
            for (int mi = 0; mi < 2; mi++) {
                const float* ap = as + (wm + mi * 16 + gid) * LDP + kb + 2 * qid;
                float2 va = *(const float2*)ap;
                float2 vb = *(const float2*)(ap + 8 * LDP);
                afr[mi][0] = __float_as_uint(va.x);
                afr[mi][1] = __float_as_uint(vb.x);
                afr[mi][2] = __float_as_uint(va.y);
                afr[mi][3] = __float_as_uint(vb.y);
            }
            uint32_t bfr[8][2];
#pragma unroll
            for (int ni = 0; ni < 8; ni++) {
                float2 vb = *(const float2*)(bs + (wn + ni * 8 + gid) * LDP + kb + 2 * qid);
                bfr[ni][0] = __float_as_uint(vb.x);
                bfr[ni][1] = __float_as_uint(vb.y);
            }
#pragma unroll
            for (int mi = 0; mi < 2; mi++)
#pragma unroll
                for (int ni = 0; ni < 8; ni++)
                    mma_tf32(acc[mi][ni], afr[mi], bfr[ni]);
        }
        __syncthreads();
        buf ^= 1;
    }

    // epilogue
    const int j0 = qid * 2, j1 = qid * 2 + 1;
#pragma unroll
    for (int mi = 0; mi < 2; mi++) {
        const int r0 = m0 + wm + mi * 16 + gid;
        const int r1 = r0 + 8;
#pragma unroll
        for (int ni = 0; ni < 8; ni++) {
            const int colb = n0 + wn + ni * 8;
            float o00 = acc[mi][ni][0] * alpha, o01 = acc[mi][ni][1] * alpha;
            float o10 = acc[mi][ni][2] * alpha, o11 = acc[mi][ni][3] * alpha;
            if (EPI == 2) {
                float bn0 = bias[colb + j0], bn1 = bias[colb + j1];
                o00 += bn0; o01 += bn1; o10 += bn0; o11 += bn1;
            }
            if (ROUND) { o00 = rtf(o00); o01 = rtf(o01); o10 = rtf(o10); o11 = rtf(o11); }
            int c0a, c1a;  // absolute output columns
            if (PERM == 1) {
                c0a = colb + perm8(j0);
                c1a = colb + perm8(j1);
            } else if (PERM == 2) {
                // true cols (colb+j0, colb+j1) are one bf16 pair -> permbf keeps them adjacent
                c0a = permbf(colb + j0);
                c1a = c0a + 1;
            } else {
                c0a = colb + j0;
                c1a = colb + j1;
            }
            Cb[(size_t)r0 * ldc + c0a] = o00;
            Cb[(size_t)r0 * ldc + c1a] = o01;
            Cb[(size_t)r1 * ldc + c0a] = o10;
            Cb[(size_t)r1 * ldc + c1a] = o11;
        }
    }
}

// ---------------- bf16 warp-MMA GEMM (V-proj, attn.V, out-proj) ----------------
// D[m,n] = sum_k A[m,k]*B[n,k] (+ epilogue). A/B bf16, K pair-permuted.
// EPI: 0=none, 1=+bias[m], 3=+bias[m]+resid (fp32 out). OUTBF: 1=bf16 pair-perm out, 0=fp32 out.
#define LDPB 20                        // u32 pitch (16 data u32 + 4 pad)
#define TILEB_BYTES (128 * LDPB * 4)   // 10240
#define MMB_SMEM (4 * TILEB_BYTES)     // 40960

template<int EPI, int OUTBF>
__global__ __launch_bounds__(256, 2) void mmb_kernel(
    const __nv_bfloat16* __restrict__ A, const __nv_bfloat16* __restrict__ B,
    void* __restrict__ Cv,
    int Kd, int lda, int ldb, int ldc,
    size_t sA, size_t sB, size_t sC,
    const float* __restrict__ bias,
    const float* __restrict__ resid, size_t sR)
{
    extern __shared__ uint32_t smu[];
    uint32_t* As[2] = { smu,                  smu + 128 * LDPB };
    uint32_t* Bs[2] = { smu + 2 * 128 * LDPB, smu + 3 * 128 * LDPB };
    const uint32_t sbase = smem_u32(smu);

    const int t = threadIdx.x;
    const int lane = t & 31, wid = t >> 5;
    const int gid = lane >> 2, qid = lane & 3;
    const int wm = (wid & 3) * 32, wn = (wid >> 2) * 64;

    const int bz = blockIdx.z;
    const __nv_bfloat16* Ab = A + (size_t)bz * sA;
    const __nv_bfloat16* Bb = B + (size_t)bz * sB;
    const int m0 = blockIdx.y * 128;
    const int n0 = blockIdx.x * 128;

    const int lrow = t >> 2;      // 0..63 (also handles lrow+64)
    const int lch  = t & 3;       // 16B chunk (8 bf16)

    float acc[2][8][4];
#pragma unroll
    for (int mi = 0; mi < 2; mi++)
#pragma unroll
        for (int ni = 0; ni < 8; ni++)
#pragma unroll
            for (int j = 0; j < 4; j++) acc[mi][ni][j] = 0.f;

    const int nslab = Kd >> 5;

    {
        const __nv_bfloat16* ga = Ab + (size_t)(m0 + lrow) * lda + lch * 8;
        const __nv_bfloat16* gb = Bb + (size_t)(n0 + lrow) * ldb + lch * 8;
        uint32_t da = sbase + (uint32_t)((lrow * LDPB + lch * 4) * 4);
        uint32_t db = da + 2u * TILEB_BYTES;
        cp_async16(da, ga);
        cp_async16(da + 64u * LDPB * 4u, ga + (size_t)64 * lda);
        cp_async16(db, gb);
        cp_async16(db + 64u * LDPB * 4u, gb + (size_t)64 * ldb);
        CP_COMMIT();
    }

    int buf = 0;
    for (int s = 0; s < nslab; s++) {
        if (s + 1 < nslab) {
            int k0 = (s + 1) << 5;
            int nb = buf ^ 1;
            const __nv_bfloat16* ga = Ab + (size_t)(m0 + lrow) * lda + k0 + lch * 8;
            const __nv_bfloat16* gb = Bb + (size_t)(n0 + lrow) * ldb + k0 + lch * 8;
            uint32_t da = sbase + (uint32_t)nb * TILEB_BYTES + (uint32_t)((lrow * LDPB + lch * 4) * 4);
            uint32_t db = da + 2u * TILEB_BYTES;
            cp_async16(da, ga);
            cp_async16(da + 64u * LDPB * 4u, ga + (size_t)64 * lda);
            cp_async16(db, gb);
            cp_async16(db + 64u * LDPB * 4u, gb + (size_t)64 * ldb);
            CP_COMMIT();
            CP_WAIT(1);
        } else {
            CP_WAIT(0);
        }
        __syncthreads();

        const uint32_t* as = As[buf];
        const uint32_t* bs = Bs[buf];
#pragma unroll
        for (int s2 = 0; s2 < 2; s2++) {
            const int kb = s2 * 8 + 2 * qid;
            uint32_t a0[2], a1[2], a2[2], a3[2];
#pragma unroll
            for (int mi = 0; mi < 2; mi++) {
                uint2 va = *(const uint2*)(as + (wm + mi * 16 + gid) * LDPB + kb);
                uint2 vb = *(const uint2*)(as + (wm + mi * 16 + gid + 8) * LDPB + kb);
                a0[mi] = va.x; a2[mi] = va.y;
                a1[mi] = vb.x; a3[mi] = vb.y;
            }
            uint2 bf[8];
#pragma unroll
            for (int ni = 0; ni < 8; ni++)
                bf[ni] = *(const uint2*)(bs + (wn + ni * 8 + gid) * LDPB + kb);
#pragma unroll
            for (int mi = 0; mi < 2; mi++)
#pragma unroll
                for (int ni = 0; ni < 8; ni++)
                    mma_bf16(acc[mi][ni], a0[mi], a1[mi], a2[mi], a3[mi], bf[ni].x, bf[ni].y);
        }
        __syncthreads();
        buf ^= 1;
    }

    // epilogue
#pragma unroll
    for (int mi = 0; mi < 2; mi++) {
        const int r0 = m0 + wm + mi * 16 + gid;
        const int r1 = r0 + 8;
        float b0 = 0.f, b1 = 0.f;
        if (EPI == 1 || EPI == 3) { b0 = bias[r0]; b1 = bias[r1]; }
#pragma unroll
        for (int ni = 0; ni < 8; ni++) {
            const int colb = n0 + wn + ni * 8;
            const int col = colb + 2 * qid;       // absolute (even) output column
            float o00 = acc[mi][ni][0] + b0, o01 = acc[mi][ni][1] + b0;
            float o10 = acc[mi][ni][2] + b1, o11 = acc[mi][ni][3] + b1;
            if (OUTBF) {
                uint32_t* Cb = (uint32_t*)Cv + (size_t)bz * (sC >> 1);
                // pair (col, col+1) -> u32 position permpair(col>>1)
                const int cp = permpair(col >> 1);
                Cb[(size_t)r0 * (ldc >> 1) + cp] = pack_bf2(o00, o01);
                Cb[(size_t)r1 * (ldc >> 1) + cp] = pack_bf2(o10, o11);
            } else {
                float* Cb = (float*)Cv + (size_t)bz * sC;
                if (EPI == 3) {
                    const float* rb = resid + (size_t)bz * sR;
                    float2 rv0 = *(const float2*)(rb + (size_t)r0 * ldc + col);
                    float2 rv1 = *(const float2*)(rb + (size_t)r1 * ldc + col);
                    o00 += rv0.x; o01 += rv0.y; o10 += rv1.x; o11 += rv1.y;
                }
                *(float2*)(Cb + (size_t)r0 * ldc + col) = make_float2(o00, o01);
                *(float2*)(Cb + (size_t)r1 * ldc + col) = make_float2(o10, o11);
            }
        }
    }
}

// ---------------- row softmax: fp32 g_sc -> bf16 g_p ----------------
__global__ __launch_bounds__(256) void softmax_kernel() {
    const float4* row = (const float4*)(g_sc + (size_t)blockIdx.x * HW);
    uint2* prow = (uint2*)(g_p + (size_t)blockIdx.x * HW);
    int t = threadIdx.x;
    float4 v[4];
    float mx = -1e30f;
#pragma unroll
    for (int i = 0; i < 4; i++) {
        v[i] = row[t + i * 256];
        mx = fmaxf(mx, fmaxf(fmaxf(v[i].x, v[i].y), fmaxf(v[i].z, v[i].w)));
    }
    __shared__ float sh[8];
#pragma unroll
    for (int o = 16; o; o >>= 1) mx = fmaxf(mx, __shfl_xor_sync(0xffffffffu, mx, o));
    if ((t & 31) == 0) sh[t >> 5] = mx;
    __syncthreads();
    mx = sh[0];
#pragma unroll
    for (int i = 1; i < 8; i++) mx = fmaxf(mx, sh[i]);

    float s = 0.f;
#pragma unroll
    for (int i = 0; i < 4; i++) {
        v[i].x = __expf(v[i].x - mx); v[i].y = __expf(v[i].y - mx);
        v[i].z = __expf(v[i].z - mx); v[i].w = __expf(v[i].w - mx);
        s += v[i].x + v[i].y + v[i].z + v[i].w;
    }
#pragma unroll
    for (int o = 16; o; o >>= 1) s += __shfl_xor_sync(0xffffffffu, s, o);
    __syncthreads();
    if ((t & 31) == 0) sh[t >> 5] = s;
    __syncthreads();
    s = 0.f;
#pragma unroll
    for (int i = 0; i < 8; i++) s += sh[i];
    float inv = 1.f / s;
#pragma unroll
    for (int i = 0; i < 4; i++) {
        uint2 o;
        o.x = pack_bf2(v[i].x * inv, v[i].y * inv);
        o.y = pack_bf2(v[i].z * inv, v[i].w * inv);
        prow[t + i * 256] = o;
    }
}

// ---------------- launch ----------------
extern "C" void kernel_launch(void* const* d_in, const int* in_sizes, int n_in,
                              void* d_out, int out_size) {
    const float* x     = (const float*)d_in[0];
    const float* gn_w  = (const float*)d_in[1];
    const float* gn_b  = (const float*)d_in[2];
    const float* qkv_w = (const float*)d_in[3];
    const float* qkv_b = (const float*)d_in[4];
    const float* out_w = (const float*)d_in[5];
    const float* out_b = (const float*)d_in[6];
    float* out = (float*)d_out;

    float *xn, *xnt, *q, *k, *sc, *wq;
    __nv_bfloat16 *xnb, *v, *p, *ao, *wvb, *wob;
    cudaGetSymbolAddress((void**)&xn,  g_xn);
    cudaGetSymbolAddress((void**)&xnt, g_xnt);
    cudaGetSymbolAddress((void**)&xnb, g_xnb);
    cudaGetSymbolAddress((void**)&q,   g_q);
    cudaGetSymbolAddress((void**)&k,   g_k);
    cudaGetSymbolAddress((void**)&v,   g_v);
    cudaGetSymbolAddress((void**)&sc,  g_sc);
    cudaGetSymbolAddress((void**)&p,   g_p);
    cudaGetSymbolAddress((void**)&ao,  g_ao);
    cudaGetSymbolAddress((void**)&wq,  g_wq);
    cudaGetSymbolAddress((void**)&wvb, g_wvb);
    cudaGetSymbolAddress((void**)&wob, g_wob);

    cudaFuncSetAttribute(mm_kernel<2,1,1>, cudaFuncAttributeMaxDynamicSharedMemorySize, MM_SMEM);
    cudaFuncSetAttribute(mm_kernel<0,2,0>, cudaFuncAttributeMaxDynamicSharedMemorySize, MM_SMEM);
    cudaFuncSetAttribute(mmb_kernel<1,1>, cudaFuncAttributeMaxDynamicSharedMemorySize, MMB_SMEM);
    cudaFuncSetAttribute(mmb_kernel<0,1>, cudaFuncAttributeMaxDynamicSharedMemorySize, MMB_SMEM);
    cudaFuncSetAttribute(mmb_kernel<3,0>, cudaFuncAttributeMaxDynamicSharedMemorySize, MMB_SMEM);

    const size_t sXN = (size_t)CCH * HW;
    const size_t sSC = (size_t)HW * HW;

    // 0) weight prep
    prep_w_kernel<<<(2 * CCH * CCH + 255) / 256, 256>>>(qkv_w, wq, 2 * CCH * CCH);
    prep_wb_kernel<<<(CCH * CCH + 255) / 256, 256>>>(qkv_w + (size_t)2 * CCH * CCH, wvb, CCH * CCH);
    prep_wb_kernel<<<(CCH * CCH + 255) / 256, 256>>>(out_w, wob, CCH * CCH);

    // 1) GroupNorm
    gn_kernel<<<BATCH * NGRP, 256>>>(x, gn_w, gn_b);
    // 2) transpose -> xnt (tf32) + xnb (bf16)
    tr_kernel<<<dim3(HW / 32, CCH / 32, BATCH), 256>>>();

    // 3) Q = xnt @ Wq^T + bq   (tf32, out elem-perm)
    mm_kernel<2,1,1><<<dim3(CCH / 128, HW / 128, BATCH), 256, MM_SMEM>>>(
        xnt, wq, q, CCH, CCH, CCH, CCH, sXN, 0, sXN, 1.f, qkv_b);
    // 4) K
    mm_kernel<2,1,1><<<dim3(CCH / 128, HW / 128, BATCH), 256, MM_SMEM>>>(
        xnt, wq + (size_t)CCH * CCH, k, CCH, CCH, CCH, CCH, sXN, 0, sXN, 1.f, qkv_b + CCH);
    // 5) V[c,j''] = Wv[c,:] . xn[:,j] + bv   (bf16)
    mmb_kernel<1,1><<<dim3(HW / 128, CCH / 128, BATCH), 256, MMB_SMEM>>>(
        wvb, xnb, v, CCH, CCH, CCH, HW, 0, sXN, sXN, qkv_b + 2 * CCH, nullptr, 0);

    // 6) scores[i,j''] = scale * Q[i,:].K[j,:]  (tf32, out at bf16-pair positions)
    mm_kernel<0,2,0><<<dim3(HW / 128, HW / 128, BATCH), 256, MM_SMEM>>>(
        q, k, sc, CCH, CCH, CCH, HW, sXN, sXN, sSC,
        0.044194173824159216f, nullptr);

    // 7) softmax -> bf16 P
    softmax_kernel<<<BATCH * HW, 256>>>();

    // 8) ao[i,c''] = P[i,:] . V[c,:]   (bf16)
    mmb_kernel<0,1><<<dim3(CCH / 128, HW / 128, BATCH), 256, MMB_SMEM>>>(
        p, v, ao, HW, HW, HW, CCH, sSC, sXN, sXN, nullptr, nullptr, 0);

    // 9) out[o,i] = Wo[o,:] . ao[i,:] + bo + xn[o,i]   (bf16 MMA, fp32 out)
    mmb_kernel<3,0><<<dim3(HW / 128, CCH / 128, BATCH), 256, MMB_SMEM>>>(
        wob, ao, out, CCH, CCH, CCH, HW, 0, sXN, sXN, out_b, xn, sXN);
}